// round 5
// baseline (speedup 1.0000x reference)
#include <cuda_runtime.h>
#include <stdint.h>

#define Bn 32
#define In 1152
#define On 10
#define Dn 16
#define Hn 10
#define Sn 922
#define ROWF 20          // padded floats per u row (80B): conflict-free float4 LDS
#define NTHREADS 256

struct Smem {
    float u[In * ROWF];        // row-major, padded; float4-addressable
    float w[In];               // ||u_i||
    float w2[In];              // ||u_i||^2
    unsigned rbits[In];        // 10-bit hypothesis mask per i
    float Mu[Hn * 16];         // Mu[h][d]
    float mm[Hn];              // ||Mu_h||^2
    float denom[Hn];
    float npart[8 * 16 * Hn];  // per-warp num partials [w][d][h]
    float dpart[8 * Hn];       // per-warp denom partials
    float lpart[8 * Hn];       // per-warp loss partials
    float losses[Hn];
    int besth;
    int idx_is64;              // runtime dtype sniff for sample_idx
};

// sqrt on the FMA pipe (avoid MUFU bottleneck: ~3.7M sqrts total).
// quake seed + 3 Newton iterations: rel err ~1e-7. x==0 -> 0 naturally.
__device__ __forceinline__ float fsqrt_nm(float x) {
    float xh = 0.5f * x;
    float r = __int_as_float(0x5f3759df - (__float_as_int(x) >> 1));
    r = r * (1.5f - xh * r * r);
    r = r * (1.5f - xh * r * r);
    r = r * (1.5f - xh * r * r);
    return x * r;
}

__global__ void __launch_bounds__(NTHREADS, 2)
ransac_kernel(const float* __restrict__ up, const int* __restrict__ sidx32,
              float* __restrict__ out)
{
    extern __shared__ float smraw[];
    Smem* sm = reinterpret_cast<Smem*>(smraw);
    const int tid = threadIdx.x;
    const int bo = blockIdx.x;
    const int b = bo / On, o = bo % On;
    const int lane = tid & 31, wrp = tid >> 5;

    // ---- zero hypothesis masks; sniff index dtype ----
    for (int i = tid; i < In; i += NTHREADS) sm->rbits[i] = 0u;
    if (tid == 0) {
        // If sample_idx is int64, odd 32-bit words are high halves == 0
        // (indices in [0,1152)). If int32, they are ~uniform indices:
        // P(8 odd words all zero) ~ 1152^-8. Deterministic per run.
        int all0 = 1;
        #pragma unroll
        for (int k = 0; k < 8; k++) all0 &= (sidx32[2 * k + 1] == 0);
        sm->idx_is64 = all0;
    }
    __syncthreads();
    const int is64 = sm->idx_is64;

    // ---- Phase A: load u slice into smem (padded rows), fused norm compute ----
    // u_predict[b,i,o,d] at b*I*O*D + i*O*D + o*D + d
    const float4* ub = reinterpret_cast<const float4*>(up + ((size_t)b * In * On + o) * Dn);
    float4* u4 = reinterpret_cast<float4*>(sm->u);
    #pragma unroll
    for (int k = 0; k < (In * 4) / NTHREADS; k++) {          // 18 exact iters
        int e = tid + k * NTHREADS;
        int i = e >> 2, q = e & 3;
        float4 v = ub[i * 40 + q];                            // O*D/4 = 40
        u4[i * 5 + q] = v;                                    // ROWF/4 = 5
        float s = v.x * v.x + v.y * v.y + v.z * v.z + v.w * v.w;
        s += __shfl_xor_sync(0xffffffffu, s, 1);
        s += __shfl_xor_sync(0xffffffffu, s, 2);
        if (q == 0) { sm->w2[i] = s; sm->w[i] = fsqrt_nm(s); }
    }

    // ---- Phase C: scatter sample_idx -> rbits (atomicOr: commutative, deterministic) ----
    // sample_idx[b,s,o,h] element offset: b*S*O*H + s*O*H + o*H + h
    {
        const size_t base = (size_t)b * Sn * On * Hn + (size_t)o * Hn;
        for (int e = tid; e < Sn * Hn; e += NTHREADS) {
            int s = e / Hn, h = e - s * Hn;
            size_t eo = base + (size_t)s * (On * Hn) + h;
            int i = is64 ? sidx32[eo << 1] : sidx32[eo];     // int64: low word (LE)
            if ((unsigned)i < (unsigned)In)                  // never fault
                atomicOr(&sm->rbits[i], 1u << h);
        }
    }
    __syncthreads();

    // ---- Phase D: num[d][h] = sum_i r*w*u ; denom[h] = sum_i r*w ----
    {
        const int q = tid & 3, ip = tid >> 2;                 // d-quad, i-partition
        float acc[4][Hn], dloc[Hn];
        #pragma unroll
        for (int h = 0; h < Hn; h++) {
            acc[0][h] = 0.f; acc[1][h] = 0.f; acc[2][h] = 0.f; acc[3][h] = 0.f;
            dloc[h] = 0.f;
        }
        #pragma unroll 2
        for (int i = ip; i < In; i += 64) {                   // 18 exact iters
            float4 uq = u4[i * 5 + q];
            unsigned bits = sm->rbits[i];
            float wi = sm->w[i];
            #pragma unroll
            for (int h = 0; h < Hn; h++) {
                float m = ((bits >> h) & 1u) ? wi : 0.0f;
                acc[0][h] = fmaf(m, uq.x, acc[0][h]);
                acc[1][h] = fmaf(m, uq.y, acc[1][h]);
                acc[2][h] = fmaf(m, uq.z, acc[2][h]);
                acc[3][h] = fmaf(m, uq.w, acc[3][h]);
                dloc[h] += m;
            }
        }
        // reduce over the 8 i-partitions within each warp (q preserved)
        #pragma unroll
        for (int off = 4; off <= 16; off <<= 1) {
            #pragma unroll
            for (int h = 0; h < Hn; h++) {
                acc[0][h] += __shfl_xor_sync(0xffffffffu, acc[0][h], off);
                acc[1][h] += __shfl_xor_sync(0xffffffffu, acc[1][h], off);
                acc[2][h] += __shfl_xor_sync(0xffffffffu, acc[2][h], off);
                acc[3][h] += __shfl_xor_sync(0xffffffffu, acc[3][h], off);
                dloc[h]   += __shfl_xor_sync(0xffffffffu, dloc[h], off);
            }
        }
        if (lane < 4) {                                       // one lane per q
            #pragma unroll
            for (int j = 0; j < 4; j++)
                #pragma unroll
                for (int h = 0; h < Hn; h++)
                    sm->npart[(wrp * 16 + (q * 4 + j)) * Hn + h] = acc[j][h];
            if (q == 0)
                #pragma unroll
                for (int h = 0; h < Hn; h++) sm->dpart[wrp * Hn + h] = dloc[h];
        }
    }
    __syncthreads();

    // ---- Phase E: final reduce -> Mu, mm ----
    float numreg = 0.f;
    int dd = 0, hh = 0;
    if (tid < 160) {
        dd = tid / Hn; hh = tid - dd * Hn;
        #pragma unroll
        for (int w8 = 0; w8 < 8; w8++) numreg += sm->npart[(w8 * 16 + dd) * Hn + hh];
    } else if (tid < 160 + Hn) {
        int h = tid - 160;
        float s = 0.f;
        #pragma unroll
        for (int w8 = 0; w8 < 8; w8++) s += sm->dpart[w8 * Hn + h];
        sm->denom[h] = s;
    }
    __syncthreads();
    if (tid < 160) sm->Mu[hh * 16 + dd] = numreg / sm->denom[hh];
    __syncthreads();
    if (tid < Hn) {
        float s = 0.f;
        #pragma unroll
        for (int d = 0; d < Dn; d++) { float m = sm->Mu[tid * 16 + d]; s = fmaf(m, m, s); }
        sm->mm[tid] = s;
    }
    __syncthreads();

    // ---- Phase F: losses[h] = sum_i sqrt(w2[i] - 2*dot(u_i,Mu_h) + mm[h]) ----
    {
        float lloc[Hn];
        float mmr[Hn];
        #pragma unroll
        for (int h = 0; h < Hn; h++) { lloc[h] = 0.f; mmr[h] = sm->mm[h]; }
        const float4* mu4 = reinterpret_cast<const float4*>(sm->Mu);
        for (int i = tid; i < In; i += NTHREADS) {
            float4 a = u4[i * 5 + 0], bb = u4[i * 5 + 1];
            float4 c = u4[i * 5 + 2], d4 = u4[i * 5 + 3];
            float ww2 = sm->w2[i];
            #pragma unroll
            for (int h = 0; h < Hn; h++) {
                float4 m0 = mu4[h * 4 + 0], m1 = mu4[h * 4 + 1];
                float4 m2 = mu4[h * 4 + 2], m3 = mu4[h * 4 + 3];
                float dot = a.x * m0.x;
                dot = fmaf(a.y, m0.y, dot);  dot = fmaf(a.z, m0.z, dot);
                dot = fmaf(a.w, m0.w, dot);  dot = fmaf(bb.x, m1.x, dot);
                dot = fmaf(bb.y, m1.y, dot); dot = fmaf(bb.z, m1.z, dot);
                dot = fmaf(bb.w, m1.w, dot); dot = fmaf(c.x, m2.x, dot);
                dot = fmaf(c.y, m2.y, dot);  dot = fmaf(c.z, m2.z, dot);
                dot = fmaf(c.w, m2.w, dot);  dot = fmaf(d4.x, m3.x, dot);
                dot = fmaf(d4.y, m3.y, dot); dot = fmaf(d4.z, m3.z, dot);
                dot = fmaf(d4.w, m3.w, dot);
                float s = fmaf(-2.0f, dot, ww2 + mmr[h]);
                s = fmaxf(s, 0.0f);
                lloc[h] += fsqrt_nm(s);
            }
        }
        #pragma unroll
        for (int off = 1; off <= 16; off <<= 1)
            #pragma unroll
            for (int h = 0; h < Hn; h++)
                lloc[h] += __shfl_xor_sync(0xffffffffu, lloc[h], off);
        if (lane == 0)
            #pragma unroll
            for (int h = 0; h < Hn; h++) sm->lpart[wrp * Hn + h] = lloc[h];
    }
    __syncthreads();
    if (tid < Hn) {
        float s = 0.f;
        #pragma unroll
        for (int w8 = 0; w8 < 8; w8++) s += sm->lpart[w8 * Hn + tid];
        sm->losses[tid] = s;
    }
    __syncthreads();
    if (tid == 0) {
        int best = 0; float bv = sm->losses[0];
        #pragma unroll
        for (int h = 1; h < Hn; h++)
            if (sm->losses[h] < bv) { bv = sm->losses[h]; best = h; }
        sm->besth = best;
    }
    __syncthreads();

    // ---- output: v[b,o,:] = Mu[:, besth] ----
    if (tid < Dn)
        out[((size_t)b * On + o) * Dn + tid] = sm->Mu[sm->besth * 16 + tid];
}

extern "C" void kernel_launch(void* const* d_in, const int* in_sizes, int n_in,
                              void* d_out, int out_size)
{
    const float* up;
    const int* si;
    // defensive input-order resolution by element counts
    if (in_sizes[0] == Bn * In * On * Dn) {
        up = (const float*)d_in[0];
        si = (const int*)d_in[1];
    } else {
        up = (const float*)d_in[1];
        si = (const int*)d_in[0];
    }
    float* out = (float*)d_out;

    cudaFuncSetAttribute(ransac_kernel,
                         cudaFuncAttributeMaxDynamicSharedMemorySize,
                         (int)sizeof(Smem));
    ransac_kernel<<<Bn * On, NTHREADS, sizeof(Smem)>>>(up, si, out);
}